// round 2
// baseline (speedup 1.0000x reference)
#include <cuda_runtime.h>

typedef unsigned long long ull;

// ---------------- scratch (no allocation allowed; __device__ globals) --------
__device__ float g_qp[32 * 1024];              // query @ W2  [B][H]
__device__ float g_ctx_part[16 * 32 * 1024];   // context partials [j][B][D]

// ---------------- helpers ----------------------------------------------------
__device__ __forceinline__ ull pack2(float lo, float hi) {
    ull r;
    asm("mov.b64 %0, {%1, %2};" : "=l"(r) : "f"(lo), "f"(hi));
    return r;
}
__device__ __forceinline__ void fma2(ull& d, ull a, ull b) {
    // packed fp32x2 FMA (sm_100+): d = a * b + d, per-lane IEEE fp32
    asm("fma.rn.f32x2 %0, %1, %2, %0;" : "+l"(d) : "l"(a), "l"(b));
}
__device__ __forceinline__ float2 unpk(ull p) {
    float2 f;
    asm("mov.b64 {%0, %1}, %2;" : "=f"(f.x), "=f"(f.y) : "l"(p));
    return f;
}
// accurate-enough tanh via MUFU ex2/rcp (err ~1e-6; hw tanh.approx too sloppy)
__device__ __forceinline__ float tanh_fast(float x) {
    float e = __expf(2.0f * x);
    return 1.0f - __fdividef(2.0f, e + 1.0f);
}

// ---------------- K1: query_proj = query @ W2  [32,1024] ---------------------
__global__ void qp_kernel(const float* __restrict__ query,
                          const float* __restrict__ W2) {
    __shared__ float sq[1024];
    int b = blockIdx.x;
    for (int i = threadIdx.x; i < 1024; i += 256) sq[i] = query[b * 1024 + i];
    __syncthreads();
    int h4 = threadIdx.x * 4;
    float4 acc = make_float4(0.f, 0.f, 0.f, 0.f);
#pragma unroll 4
    for (int d = 0; d < 1024; d++) {
        float q = sq[d];
        float4 wv = *(const float4*)(W2 + (size_t)d * 1024 + h4);
        acc.x += q * wv.x; acc.y += q * wv.y; acc.z += q * wv.z; acc.w += q * wv.w;
    }
    *(float4*)(g_qp + b * 1024 + h4) = acc;
}

// ---------------- K2: fused  scores = tanh(values@W1 + qp) . v ---------------
// 128x128x8 fp32 tile GEMM, f32x2 packed FMA, H looped inside the block so the
// [B,S,H] intermediate never exists; per-row score accumulated in registers.
__global__ __launch_bounds__(256, 2)
void scores_kernel(const float* __restrict__ values,
                   const float* __restrict__ W1,
                   const float* __restrict__ v,
                   float* __restrict__ scores) {
    __shared__ float As[8][128];      // values tile, transposed (K-major)
    __shared__ float Bs[8][128];      // W1 tile
    __shared__ float qv_s[128];
    __shared__ float vv_s[128];
    __shared__ float red[128][17];    // score reduction (pad 17: no conflicts)

    const int tid  = threadIdx.x;
    const int row0 = blockIdx.x * 128;          // 512 blocks, rows within one b
    const int b    = row0 >> 11;
    const float* A  = values + (size_t)row0 * 1024;
    const float* qp = g_qp + b * 1024;

    const int tx  = tid & 15, ty = tid >> 4;
    const int tx4 = tx * 4,  ty4 = ty * 4;
    const int arow = tid >> 1, acol = (tid & 1) * 4;   // A-tile load map
    const int brow = tid >> 5, bcol = (tid & 31) * 4;  // B-tile load map

    float srow[8];
#pragma unroll
    for (int i = 0; i < 8; i++) srow[i] = 0.f;

    for (int n0 = 0; n0 < 1024; n0 += 128) {
        __syncthreads();  // previous epilogue done with qv_s/vv_s
        if (tid < 128) { qv_s[tid] = qp[n0 + tid]; vv_s[tid] = v[n0 + tid]; }

        ull acc[8][4];
#pragma unroll
        for (int i = 0; i < 8; i++)
#pragma unroll
            for (int j = 0; j < 4; j++) acc[i][j] = 0ull;

        const float* Bp = W1 + n0;
        for (int k0 = 0; k0 < 1024; k0 += 8) {
            float4 av = *(const float4*)(A + (size_t)arow * 1024 + k0 + acol);
            float4 bv = *(const float4*)(Bp + (size_t)(k0 + brow) * 1024 + bcol);
            __syncthreads();
            As[acol + 0][arow] = av.x;
            As[acol + 1][arow] = av.y;
            As[acol + 2][arow] = av.z;
            As[acol + 3][arow] = av.w;
            *(float4*)&Bs[brow][bcol] = bv;
            __syncthreads();
#pragma unroll
            for (int kk = 0; kk < 8; kk++) {
                float4 aA = *(const float4*)&As[kk][ty4];
                float4 aB = *(const float4*)&As[kk][64 + ty4];
                ulonglong2 bA = *(const ulonglong2*)&Bs[kk][tx4];       // col pairs, free
                ulonglong2 bB = *(const ulonglong2*)&Bs[kk][64 + tx4];
                float ar[8] = {aA.x, aA.y, aA.z, aA.w, aB.x, aB.y, aB.z, aB.w};
#pragma unroll
                for (int i = 0; i < 8; i++) {
                    ull ad = pack2(ar[i], ar[i]);
                    fma2(acc[i][0], ad, bA.x);
                    fma2(acc[i][1], ad, bA.y);
                    fma2(acc[i][2], ad, bB.x);
                    fma2(acc[i][3], ad, bB.y);
                }
            }
        }
        // epilogue: tanh(acc + qp) * v, fold into per-row score accumulators
#pragma unroll
        for (int jp = 0; jp < 4; jp++) {
            int c0 = (jp < 2) ? (tx4 + jp * 2) : (64 + tx4 + (jp - 2) * 2);
            float q0 = qv_s[c0], q1 = qv_s[c0 + 1];
            float v0 = vv_s[c0], v1 = vv_s[c0 + 1];
#pragma unroll
            for (int i = 0; i < 8; i++) {
                float2 p = unpk(acc[i][jp]);
                srow[i] += tanh_fast(p.x + q0) * v0 + tanh_fast(p.y + q1) * v1;
            }
        }
    }

    // deterministic cross-thread score reduction
    __syncthreads();
#pragma unroll
    for (int i = 0; i < 8; i++) {
        int r = (i < 4) ? (ty4 + i) : (64 + ty4 + i - 4);
        red[r][tx] = srow[i];
    }
    __syncthreads();
    if (tid < 128) {
        float s = 0.f;
#pragma unroll
        for (int x = 0; x < 16; x++) s += red[tid][x];
        scores[row0 + tid] = s;
    }
}

// ---------------- K3: softmax over S (in-place in the output buffer) ---------
__global__ void softmax_kernel(float* __restrict__ w) {
    int b = blockIdx.x;
    float* p = w + b * 2048;
    int t = threadIdx.x;                       // 1024 threads, 2 elems each
    __shared__ float sm[32];

    float a0 = p[t], a1 = p[t + 1024];
    float m = fmaxf(a0, a1);
#pragma unroll
    for (int o = 16; o; o >>= 1) m = fmaxf(m, __shfl_xor_sync(0xffffffffu, m, o));
    if ((t & 31) == 0) sm[t >> 5] = m;
    __syncthreads();
    if (t < 32) {
        float mm = sm[t];
#pragma unroll
        for (int o = 16; o; o >>= 1) mm = fmaxf(mm, __shfl_xor_sync(0xffffffffu, mm, o));
        sm[t] = mm;
    }
    __syncthreads();
    m = sm[0];
    __syncthreads();

    float e0 = __expf(a0 - m), e1 = __expf(a1 - m);
    float s = e0 + e1;
#pragma unroll
    for (int o = 16; o; o >>= 1) s += __shfl_xor_sync(0xffffffffu, s, o);
    if ((t & 31) == 0) sm[t >> 5] = s;
    __syncthreads();
    if (t < 32) {
        float ss = sm[t];
#pragma unroll
        for (int o = 16; o; o >>= 1) ss += __shfl_xor_sync(0xffffffffu, ss, o);
        sm[t] = ss;
    }
    __syncthreads();
    float inv = 1.0f / sm[0];
    p[t] = e0 * inv;
    p[t + 1024] = e1 * inv;
}

// ---------------- K4/K5: context = w @ values (two-stage, deterministic) -----
__global__ void ctx_part_kernel(const float* __restrict__ values,
                                const float* __restrict__ w) {
    int b = blockIdx.x, j = blockIdx.y;
    __shared__ float ws[128];
    int t = threadIdx.x;                       // 256 threads cover D via float4
    if (t < 128) ws[t] = w[b * 2048 + j * 128 + t];
    __syncthreads();
    const float* V = values + ((size_t)(b * 2048 + j * 128)) * 1024 + t * 4;
    float4 acc = make_float4(0.f, 0.f, 0.f, 0.f);
#pragma unroll 8
    for (int s = 0; s < 128; s++) {
        float4 x = *(const float4*)(V + (size_t)s * 1024);
        float c = ws[s];
        acc.x += c * x.x; acc.y += c * x.y; acc.z += c * x.z; acc.w += c * x.w;
    }
    *(float4*)&g_ctx_part[((size_t)j * 32 + b) * 1024 + t * 4] = acc;
}

__global__ void ctx_reduce_kernel(float* __restrict__ ctx) {
    int b = blockIdx.x, t = threadIdx.x;       // 256 threads
    float4 acc = make_float4(0.f, 0.f, 0.f, 0.f);
#pragma unroll
    for (int j = 0; j < 16; j++) {
        float4 x = *(const float4*)&g_ctx_part[((size_t)j * 32 + b) * 1024 + t * 4];
        acc.x += x.x; acc.y += x.y; acc.z += x.z; acc.w += x.w;
    }
    *(float4*)(ctx + b * 1024 + t * 4) = acc;
}

// ---------------- launch ------------------------------------------------------
extern "C" void kernel_launch(void* const* d_in, const int* in_sizes, int n_in,
                              void* d_out, int out_size) {
    const float* query  = (const float*)d_in[0];   // [32,1024]
    const float* values = (const float*)d_in[1];   // [32,2048,1024]
    const float* W1     = (const float*)d_in[2];   // [1024,1024]
    const float* W2     = (const float*)d_in[3];   // [1024,1024]
    const float* v      = (const float*)d_in[4];   // [1024]

    float* ctx     = (float*)d_out;                // [32,1024]
    float* weights = (float*)d_out + 32 * 1024;    // [32,2048]

    qp_kernel<<<32, 256>>>(query, W2);
    scores_kernel<<<512, 256>>>(values, W1, v, weights);
    softmax_kernel<<<32, 1024>>>(weights);
    ctx_part_kernel<<<dim3(32, 16), 256>>>(values, weights);
    ctx_reduce_kernel<<<32, 256>>>(ctx);
}

// round 4
// speedup vs baseline: 3.6295x; 3.6295x over previous
#include <cuda_runtime.h>
#include <cuda_bf16.h>
#include <cstdint>

typedef unsigned int u32; typedef unsigned long long u64; typedef unsigned short u16;

// ---------------- scratch (__device__ globals; no runtime allocation) --------
__device__ float g_qp[32 * 1024];
__device__ float g_ctx_part[16 * 32 * 1024];
__device__ __align__(16) u16 g_vh[67108864];     // values hi bf16 [65536][1024]
__device__ __align__(16) u16 g_vl[67108864];     // values lo bf16
__device__ __align__(16) u16 g_w1t_h[1048576];   // W1^T hi bf16 [H][D]
__device__ __align__(16) u16 g_w1t_l[1048576];   // W1^T lo bf16

// ---------------- helpers ----------------------------------------------------
__device__ __forceinline__ u32 smem_u32(const void* p) {
    u32 a;
    asm("{ .reg .u64 t; cvta.to.shared.u64 t, %1; cvt.u32.u64 %0, t; }" : "=r"(a) : "l"(p));
    return a;
}
#define CP_ASYNC(dst, src) \
    asm volatile("cp.async.cg.shared.global [%0], [%1], 16;" :: "r"(dst), "l"(src) : "memory")
#define CP_COMMIT() asm volatile("cp.async.commit_group;" ::: "memory")
#define CP_WAIT(n)  asm volatile("cp.async.wait_group %0;" :: "n"(n) : "memory")

__device__ __forceinline__ void ldsm4(u32 (&r)[4], u32 addr) {
    asm volatile("ldmatrix.sync.aligned.m8n8.x4.shared.b16 {%0,%1,%2,%3}, [%4];"
                 : "=r"(r[0]), "=r"(r[1]), "=r"(r[2]), "=r"(r[3]) : "r"(addr));
}
__device__ __forceinline__ void mma16816(float* c, const u32* a, const u32* b) {
    asm volatile(
        "mma.sync.aligned.m16n8k16.row.col.f32.bf16.bf16.f32 "
        "{%0,%1,%2,%3}, {%4,%5,%6,%7}, {%8,%9}, {%0,%1,%2,%3};"
        : "+f"(c[0]), "+f"(c[1]), "+f"(c[2]), "+f"(c[3])
        : "r"(a[0]), "r"(a[1]), "r"(a[2]), "r"(a[3]), "r"(b[0]), "r"(b[1]));
}

__device__ __forceinline__ u16 f2bf(float x) { return __bfloat16_as_ushort(__float2bfloat16_rn(x)); }
__device__ __forceinline__ float bf2f(u16 u) { return __bfloat162float(__ushort_as_bfloat16(u)); }
__device__ __forceinline__ float tanh_fast(float x) {
    float e = __expf(2.0f * x);
    return 1.0f - __fdividef(2.0f, e + 1.0f);
}

// ---------------- K1: query_proj = query @ W2 --------------------------------
__global__ void qp_kernel(const float* __restrict__ query, const float* __restrict__ W2) {
    __shared__ float sq[1024];
    int hc = blockIdx.x, b = blockIdx.y;
    for (int i = threadIdx.x; i < 1024; i += 256) sq[i] = query[b * 1024 + i];
    __syncthreads();
    int h = hc * 256 + threadIdx.x;
    float acc = 0.f;
#pragma unroll 8
    for (int d = 0; d < 1024; d++) acc += sq[d] * W2[(size_t)d * 1024 + h];
    g_qp[b * 1024 + h] = acc;
}

// ---------------- K2: fp32 -> bf16 hi/lo converts ----------------------------
__global__ void conv_values_kernel(const float* __restrict__ src) {
    u32 i = blockIdx.x * 256u + threadIdx.x;
    float4 x = ((const float4*)src)[i];
    u16 h0 = f2bf(x.x), h1 = f2bf(x.y), h2 = f2bf(x.z), h3 = f2bf(x.w);
    u16 l0 = f2bf(x.x - bf2f(h0)), l1 = f2bf(x.y - bf2f(h1));
    u16 l2 = f2bf(x.z - bf2f(h2)), l3 = f2bf(x.w - bf2f(h3));
    ((uint2*)g_vh)[i] = make_uint2((u32)h0 | ((u32)h1 << 16), (u32)h2 | ((u32)h3 << 16));
    ((uint2*)g_vl)[i] = make_uint2((u32)l0 | ((u32)l1 << 16), (u32)l2 | ((u32)l3 << 16));
}

__global__ void conv_w1_kernel(const float* __restrict__ W1) {
    __shared__ float t[32][33];
    int d0 = blockIdx.x * 32, h0 = blockIdx.y * 32;
    int tx = threadIdx.x, ty = threadIdx.y;  // 32 x 8
#pragma unroll
    for (int i = 0; i < 4; i++) {
        int d = ty * 4 + i;
        t[d][tx] = W1[(size_t)(d0 + d) * 1024 + h0 + tx];
    }
    __syncthreads();
#pragma unroll
    for (int i = 0; i < 4; i++) {
        int h = ty * 4 + i;
        float x = t[tx][h];
        u16 hi = f2bf(x);
        u16 lo = f2bf(x - bf2f(hi));
        g_w1t_h[(size_t)(h0 + h) * 1024 + d0 + tx] = hi;
        g_w1t_l[(size_t)(h0 + h) * 1024 + d0 + tx] = lo;
    }
}

// ---------------- K3: mma.sync fused scores ----------------------------------
// Block: M=128, N=128-chunk x8, Kc=32, 2-stage cp.async pipeline.
// SMEM stage: Ah|Al|Bh|Bl, each 128 rows x 32 bf16, pitch 80B.
#define PITCH      80
#define MAT_BYTES  (128 * PITCH)        // 10240
#define STAGE_B    (4 * MAT_BYTES)      // 40960
#define DYN_BYTES  (2 * STAGE_B)        // 81920

__device__ __forceinline__ void issue_stage(u32 sstage, int tid, u32 m0, u32 n0, int kt) {
    const u32 k0 = (u32)kt * 32u;
    const u32 rr  = (u32)(tid >> 2);       // 0..63
    const u32 j16 = (u32)(tid & 3) * 16u;  // dst byte offset
    const u32 col = (u32)(tid & 3) * 8u;   // src element offset
#pragma unroll
    for (int i = 0; i < 8; i++) {
        const u32 mat = (u32)(i >> 1);
        const u32 r = rr + (u32)(i & 1) * 64u;
        const u32 dst = sstage + mat * MAT_BYTES + r * PITCH + j16;
        const u16* src;
        if (mat == 0)      src = g_vh    + ((size_t)(m0 + r) * 1024 + k0 + col);
        else if (mat == 1) src = g_vl    + ((size_t)(m0 + r) * 1024 + k0 + col);
        else if (mat == 2) src = g_w1t_h + ((size_t)(n0 + r) * 1024 + k0 + col);
        else               src = g_w1t_l + ((size_t)(n0 + r) * 1024 + k0 + col);
        CP_ASYNC(dst, src);
    }
}

__global__ __launch_bounds__(256, 2)
void scores_mma(const float* __restrict__ vvec, float* __restrict__ scores) {
    extern __shared__ __align__(16) char dyn[];
    const u32 dynb = smem_u32(dyn);

    __shared__ float qs[128], vs[128];
    __shared__ float red[2][128];

    const int tid = threadIdx.x;
    const int lane = tid & 31;
    const int wid = tid >> 5;
    const int wm = wid & 3;          // 4 m-warps (32 rows each)
    const int wn = wid >> 2;         // 2 n-warps (64 cols each)
    const u32 m0 = blockIdx.x * 128u;
    const int b = (int)(m0 >> 11);

    // per-thread ldmatrix base offsets (within a stage)
    const u32 a_off = (u32)(wm * 32 + (lane & 15)) * PITCH + (u32)((lane >> 4) << 4);
    const u32 b_off = 2u * MAT_BYTES +
                      (u32)(wn * 64 + ((lane >> 4) << 3) + (lane & 7)) * PITCH +
                      (u32)(((lane >> 3) & 1) << 4);

    float srow[4] = {0.f, 0.f, 0.f, 0.f};

    for (int hc = 0; hc < 8; hc++) {
        const u32 n0 = (u32)hc * 128u;
        __syncthreads();                      // prev epilogue done with qs/vs
        if (tid < 128) {
            qs[tid] = g_qp[b * 1024 + (int)n0 + tid];
            vs[tid] = vvec[(int)n0 + tid];
        }

        float acc[2][8][4];
#pragma unroll
        for (int tm = 0; tm < 2; tm++)
#pragma unroll
            for (int tn = 0; tn < 8; tn++)
#pragma unroll
                for (int q = 0; q < 4; q++) acc[tm][tn][q] = 0.f;

        issue_stage(dynb, tid, m0, n0, 0); CP_COMMIT();
        issue_stage(dynb + STAGE_B, tid, m0, n0, 1); CP_COMMIT();

        for (int t = 0; t < 32; t++) {
            CP_WAIT(1);
            __syncthreads();
            const u32 base = dynb + (u32)(t & 1) * STAGE_B;
            const u32 a_addr = base + a_off;
            const u32 b_addr = base + b_off;
#pragma unroll
            for (int kk = 0; kk < 2; kk++) {
                const u32 koff = (u32)kk << 5;
                u32 ah[2][4], al[2][4];
#pragma unroll
                for (int tm = 0; tm < 2; tm++) {
                    ldsm4(ah[tm], a_addr + (u32)tm * (16 * PITCH) + koff);
                    ldsm4(al[tm], a_addr + MAT_BYTES + (u32)tm * (16 * PITCH) + koff);
                }
#pragma unroll
                for (int nh = 0; nh < 2; nh++) {
                    u32 bh[2][4], bl[2][4];
#pragma unroll
                    for (int p = 0; p < 2; p++) {
                        const u32 off = (u32)(nh * 32 + p * 16) * PITCH + koff;
                        ldsm4(bh[p], b_addr + off);
                        ldsm4(bl[p], b_addr + MAT_BYTES + off);
                    }
#pragma unroll
                    for (int p = 0; p < 2; p++)
#pragma unroll
                        for (int q = 0; q < 2; q++) {
                            const int tn = nh * 4 + p * 2 + q;
#pragma unroll
                            for (int tm = 0; tm < 2; tm++) {
                                mma16816(acc[tm][tn], ah[tm], &bh[p][q * 2]);
                                mma16816(acc[tm][tn], al[tm], &bh[p][q * 2]);
                                mma16816(acc[tm][tn], ah[tm], &bl[p][q * 2]);
                            }
                        }
                }
            }
            __syncthreads();
            if (t + 2 < 32) issue_stage(dynb + (u32)(t & 1) * STAGE_B, tid, m0, n0, t + 2);
            CP_COMMIT();
        }

        // epilogue: tanh(acc + qp) * v into per-row score registers
#pragma unroll
        for (int tm = 0; tm < 2; tm++)
#pragma unroll
            for (int tn = 0; tn < 8; tn++) {
                const int c0 = wn * 64 + tn * 8 + (lane & 3) * 2;
                const float q0 = qs[c0], q1 = qs[c0 + 1];
                const float v0 = vs[c0], v1 = vs[c0 + 1];
                srow[tm * 2 + 0] += tanh_fast(acc[tm][tn][0] + q0) * v0 +
                                    tanh_fast(acc[tm][tn][1] + q1) * v1;
                srow[tm * 2 + 1] += tanh_fast(acc[tm][tn][2] + q0) * v0 +
                                    tanh_fast(acc[tm][tn][3] + q1) * v1;
            }
    }

    // reduce across the 4-thread quads sharing rows (deterministic)
#pragma unroll
    for (int i = 0; i < 4; i++) {
        srow[i] += __shfl_xor_sync(0xffffffffu, srow[i], 1);
        srow[i] += __shfl_xor_sync(0xffffffffu, srow[i], 2);
    }
    __syncthreads();
    if ((lane & 3) == 0) {
        const int r0 = wm * 32 + (lane >> 2);
        red[wn][r0]      = srow[0];
        red[wn][r0 + 8]  = srow[1];
        red[wn][r0 + 16] = srow[2];
        red[wn][r0 + 24] = srow[3];
    }
    __syncthreads();
    if (tid < 128) scores[m0 + tid] = red[0][tid] + red[1][tid];
}

// ---------------- K4: softmax over S -----------------------------------------
__global__ void softmax_kernel(float* __restrict__ w) {
    int b = blockIdx.x;
    float* p = w + b * 2048;
    int t = threadIdx.x;
    __shared__ float sm[32];
    float a0 = p[t], a1 = p[t + 1024];
    float m = fmaxf(a0, a1);
#pragma unroll
    for (int o = 16; o; o >>= 1) m = fmaxf(m, __shfl_xor_sync(0xffffffffu, m, o));
    if ((t & 31) == 0) sm[t >> 5] = m;
    __syncthreads();
    if (t < 32) {
        float mm = sm[t];
#pragma unroll
        for (int o = 16; o; o >>= 1) mm = fmaxf(mm, __shfl_xor_sync(0xffffffffu, mm, o));
        sm[t] = mm;
    }
    __syncthreads();
    m = sm[0];
    __syncthreads();
    float e0 = __expf(a0 - m), e1 = __expf(a1 - m);
    float s = e0 + e1;
#pragma unroll
    for (int o = 16; o; o >>= 1) s += __shfl_xor_sync(0xffffffffu, s, o);
    if ((t & 31) == 0) sm[t >> 5] = s;
    __syncthreads();
    if (t < 32) {
        float ss = sm[t];
#pragma unroll
        for (int o = 16; o; o >>= 1) ss += __shfl_xor_sync(0xffffffffu, ss, o);
        sm[t] = ss;
    }
    __syncthreads();
    float inv = 1.0f / sm[0];
    p[t] = e0 * inv;
    p[t + 1024] = e1 * inv;
}

// ---------------- K5/K6: context = w @ values --------------------------------
__global__ void ctx_part_kernel(const float* __restrict__ values, const float* __restrict__ w) {
    int b = blockIdx.x, j = blockIdx.y;
    __shared__ float ws[128];
    int t = threadIdx.x;
    if (t < 128) ws[t] = w[b * 2048 + j * 128 + t];
    __syncthreads();
    const float* V = values + ((size_t)(b * 2048 + j * 128)) * 1024 + t * 4;
    float4 acc = make_float4(0.f, 0.f, 0.f, 0.f);
#pragma unroll 8
    for (int s = 0; s < 128; s++) {
        float4 x = *(const float4*)(V + (size_t)s * 1024);
        float c = ws[s];
        acc.x += c * x.x; acc.y += c * x.y; acc.z += c * x.z; acc.w += c * x.w;
    }
    *(float4*)&g_ctx_part[((size_t)j * 32 + b) * 1024 + t * 4] = acc;
}

__global__ void ctx_reduce_kernel(float* __restrict__ ctx) {
    int b = blockIdx.x, t = threadIdx.x;
    float4 acc = make_float4(0.f, 0.f, 0.f, 0.f);
#pragma unroll
    for (int j = 0; j < 16; j++) {
        float4 x = *(const float4*)&g_ctx_part[((size_t)j * 32 + b) * 1024 + t * 4];
        acc.x += x.x; acc.y += x.y; acc.z += x.z; acc.w += x.w;
    }
    *(float4*)(ctx + b * 1024 + t * 4) = acc;
}

// ---------------- launch ------------------------------------------------------
extern "C" void kernel_launch(void* const* d_in, const int* in_sizes, int n_in,
                              void* d_out, int out_size) {
    const float* query  = (const float*)d_in[0];
    const float* values = (const float*)d_in[1];
    const float* W1     = (const float*)d_in[2];
    const float* W2     = (const float*)d_in[3];
    const float* v      = (const float*)d_in[4];

    float* ctx     = (float*)d_out;
    float* weights = (float*)d_out + 32 * 1024;

    cudaFuncSetAttribute(scores_mma, cudaFuncAttributeMaxDynamicSharedMemorySize, DYN_BYTES);

    qp_kernel<<<dim3(4, 32), 256>>>(query, W2);
    conv_values_kernel<<<65536, 256>>>(values);
    conv_w1_kernel<<<dim3(32, 32), dim3(32, 8)>>>(W1);
    scores_mma<<<512, 256, DYN_BYTES>>>(v, weights);
    softmax_kernel<<<32, 1024>>>(weights);
    ctx_part_kernel<<<dim3(32, 16), 256>>>(values, weights);
    ctx_reduce_kernel<<<32, 256>>>(ctx);
}

// round 5
// speedup vs baseline: 4.2656x; 1.1753x over previous
#include <cuda_runtime.h>
#include <cuda_bf16.h>
#include <cstdint>

typedef unsigned int u32; typedef unsigned long long u64; typedef unsigned short u16;

// ---------------- scratch (__device__ globals; no runtime allocation) --------
__device__ float g_qp[32 * 1024];
__device__ float g_ctx_part[16 * 32 * 1024];
__device__ __align__(16) u16 g_vh[67108864];     // values hi bf16 [65536][1024]
__device__ __align__(16) u16 g_vl[67108864];     // values lo bf16
__device__ __align__(16) u16 g_w1t_h[1048576];   // W1^T hi bf16 [H][D]
__device__ __align__(16) u16 g_w1t_l[1048576];   // W1^T lo bf16

// ---------------- helpers ----------------------------------------------------
__device__ __forceinline__ u32 smem_u32(const void* p) {
    u32 a;
    asm("{ .reg .u64 t; cvta.to.shared.u64 t, %1; cvt.u32.u64 %0, t; }" : "=r"(a) : "l"(p));
    return a;
}
#define CP_ASYNC(dst, src) \
    asm volatile("cp.async.cg.shared.global [%0], [%1], 16;" :: "r"(dst), "l"(src) : "memory")
#define CP_COMMIT() asm volatile("cp.async.commit_group;" ::: "memory")
#define CP_WAIT(n)  asm volatile("cp.async.wait_group %0;" :: "n"(n) : "memory")

__device__ __forceinline__ void ldsm4(u32 (&r)[4], u32 addr) {
    asm volatile("ldmatrix.sync.aligned.m8n8.x4.shared.b16 {%0,%1,%2,%3}, [%4];"
                 : "=r"(r[0]), "=r"(r[1]), "=r"(r[2]), "=r"(r[3]) : "r"(addr));
}
__device__ __forceinline__ void mma16816(float* c, const u32* a, const u32* b) {
    asm volatile(
        "mma.sync.aligned.m16n8k16.row.col.f32.bf16.bf16.f32 "
        "{%0,%1,%2,%3}, {%4,%5,%6,%7}, {%8,%9}, {%0,%1,%2,%3};"
        : "+f"(c[0]), "+f"(c[1]), "+f"(c[2]), "+f"(c[3])
        : "r"(a[0]), "r"(a[1]), "r"(a[2]), "r"(a[3]), "r"(b[0]), "r"(b[1]));
}

__device__ __forceinline__ u16 f2bf(float x) { return __bfloat16_as_ushort(__float2bfloat16_rn(x)); }
__device__ __forceinline__ float bf2f(u16 u) { return __bfloat162float(__ushort_as_bfloat16(u)); }
__device__ __forceinline__ float tanh_fast(float x) {
    float e = __expf(2.0f * x);
    return 1.0f - __fdividef(2.0f, e + 1.0f);
}

// ---------------- K1: query_proj = query @ W2 --------------------------------
__global__ void qp_kernel(const float* __restrict__ query, const float* __restrict__ W2) {
    __shared__ float sq[1024];
    int hc = blockIdx.x, b = blockIdx.y;
    for (int i = threadIdx.x; i < 1024; i += 256) sq[i] = query[b * 1024 + i];
    __syncthreads();
    int h = hc * 256 + threadIdx.x;
    float acc = 0.f;
#pragma unroll 8
    for (int d = 0; d < 1024; d++) acc += sq[d] * W2[(size_t)d * 1024 + h];
    g_qp[b * 1024 + h] = acc;
}

// ---------------- K2: fp32 -> bf16 hi/lo converts ----------------------------
__global__ void conv_values_kernel(const float* __restrict__ src) {
    u32 i = blockIdx.x * 256u + threadIdx.x;
    float4 x = ((const float4*)src)[i];
    u16 h0 = f2bf(x.x), h1 = f2bf(x.y), h2 = f2bf(x.z), h3 = f2bf(x.w);
    u16 l0 = f2bf(x.x - bf2f(h0)), l1 = f2bf(x.y - bf2f(h1));
    u16 l2 = f2bf(x.z - bf2f(h2)), l3 = f2bf(x.w - bf2f(h3));
    ((uint2*)g_vh)[i] = make_uint2((u32)h0 | ((u32)h1 << 16), (u32)h2 | ((u32)h3 << 16));
    ((uint2*)g_vl)[i] = make_uint2((u32)l0 | ((u32)l1 << 16), (u32)l2 | ((u32)l3 << 16));
}

__global__ void conv_w1_kernel(const float* __restrict__ W1) {
    __shared__ float t[32][33];
    int d0 = blockIdx.x * 32, h0 = blockIdx.y * 32;
    int tx = threadIdx.x, ty = threadIdx.y;  // 32 x 8
#pragma unroll
    for (int i = 0; i < 4; i++) {
        int d = ty * 4 + i;
        t[d][tx] = W1[(size_t)(d0 + d) * 1024 + h0 + tx];
    }
    __syncthreads();
#pragma unroll
    for (int i = 0; i < 4; i++) {
        int h = ty * 4 + i;
        float x = t[tx][h];
        u16 hi = f2bf(x);
        u16 lo = f2bf(x - bf2f(hi));
        g_w1t_h[(size_t)(h0 + h) * 1024 + d0 + tx] = hi;
        g_w1t_l[(size_t)(h0 + h) * 1024 + d0 + tx] = lo;
    }
}

// ---------------- K3: mma.sync fused scores (4-stage, swizzled) --------------
// Block: M=128, N=256-chunk x4, Kc=32 per stage, 512 threads, warp tile 32x64.
// Stage layout (swizzled, 64B rows): AH 8K | AL 8K | BH 16K | BL 16K = 48K.
#define AH_OFF   0
#define AL_OFF   8192
#define BH_OFF   16384
#define BL_OFF   32768
#define STAGE_B  49152
#define DYN_BYTES (4 * STAGE_B)    // 196608

__device__ __forceinline__ void issue_stage(u32 sstage, int tid, u32 m0, u32 n0, int kt) {
    const u32 k0 = (u32)kt << 5;
    const u32 r = (u32)tid >> 2, c = (u32)tid & 3;
    const u32 swz = (c ^ ((r >> 1) & 3)) << 4;
    const u32 dstA = sstage + r * 64 + swz;
    const size_t soA = (size_t)(m0 + r) * 1024 + k0 + c * 8;
    CP_ASYNC(dstA + AH_OFF, g_vh + soA);
    CP_ASYNC(dstA + AL_OFF, g_vl + soA);
#pragma unroll
    for (int j = 0; j < 2; j++) {
        const u32 rb = r + (u32)j * 128u;          // (rb>>1)&3 == (r>>1)&3
        const u32 dstB = sstage + BH_OFF + rb * 64 + swz;
        const size_t soB = (size_t)(n0 + rb) * 1024 + k0 + c * 8;
        CP_ASYNC(dstB, g_w1t_h + soB);
        CP_ASYNC(dstB + (BL_OFF - BH_OFF), g_w1t_l + soB);
    }
}

__global__ __launch_bounds__(512, 1)
void scores_mma(const float* __restrict__ vvec, float* __restrict__ scores) {
    extern __shared__ __align__(16) char dyn[];
    const u32 dynb = smem_u32(dyn);

    __shared__ float qs[256], vs[256];
    __shared__ float red[4][128];

    const int tid = threadIdx.x;
    const int lane = tid & 31;
    const int wid = tid >> 5;
    const int wm = wid & 3;          // 4 m-warps (32 rows each)
    const int wn = wid >> 2;         // 4 n-warps (64 cols each)
    const u32 m0 = blockIdx.x * 128u;
    const int b = (int)(m0 >> 11);

    // per-thread ldmatrix offsets (swizzle keys invariant under tm/nh/p shifts)
    const u32 rA0 = (u32)(wm * 32 + (lane & 15));
    const u32 keyA = (rA0 >> 1) & 3;
    u32 a_base[2], aswz[2];
#pragma unroll
    for (int tm = 0; tm < 2; tm++) a_base[tm] = (rA0 + (u32)tm * 16u) * 64u;
#pragma unroll
    for (int kk = 0; kk < 2; kk++)
        aswz[kk] = (((u32)(lane >> 4) | ((u32)kk << 1)) ^ keyA) << 4;

    const u32 rB0 = (u32)(wn * 64 + ((lane >> 4) << 3) + (lane & 7));
    const u32 keyB = (rB0 >> 1) & 3;
    u32 b_base[2][2], bswz[2];
#pragma unroll
    for (int nh = 0; nh < 2; nh++)
#pragma unroll
        for (int p = 0; p < 2; p++)
            b_base[nh][p] = (rB0 + (u32)(nh * 32 + p * 16)) * 64u;
#pragma unroll
    for (int kk = 0; kk < 2; kk++)
        bswz[kk] = (((u32)((lane >> 3) & 1) | ((u32)kk << 1)) ^ keyB) << 4;

    float srow[4] = {0.f, 0.f, 0.f, 0.f};

    for (int hc = 0; hc < 4; hc++) {
        const u32 n0 = (u32)hc * 256u;
        __syncthreads();                      // prev epilogue done with qs/vs
        if (tid < 256) {
            qs[tid] = g_qp[b * 1024 + (int)n0 + tid];
            vs[tid] = vvec[(int)n0 + tid];
        }

        float acc[2][8][4];
#pragma unroll
        for (int tm = 0; tm < 2; tm++)
#pragma unroll
            for (int tn = 0; tn < 8; tn++)
#pragma unroll
                for (int q = 0; q < 4; q++) acc[tm][tn][q] = 0.f;

        issue_stage(dynb + 0u * STAGE_B, tid, m0, n0, 0); CP_COMMIT();
        issue_stage(dynb + 1u * STAGE_B, tid, m0, n0, 1); CP_COMMIT();
        issue_stage(dynb + 2u * STAGE_B, tid, m0, n0, 2); CP_COMMIT();

        for (int t = 0; t < 32; t++) {
            CP_WAIT(2);
            __syncthreads();
            const u32 base = dynb + (u32)(t & 3) * STAGE_B;
#pragma unroll
            for (int kk = 0; kk < 2; kk++) {
                u32 ah[2][4], al[2][4];
#pragma unroll
                for (int tm = 0; tm < 2; tm++) {
                    ldsm4(ah[tm], base + AH_OFF + a_base[tm] + aswz[kk]);
                    ldsm4(al[tm], base + AL_OFF + a_base[tm] + aswz[kk]);
                }
#pragma unroll
                for (int nh = 0; nh < 2; nh++) {
                    u32 bh[2][4], bl[2][4];
#pragma unroll
                    for (int p = 0; p < 2; p++) {
                        ldsm4(bh[p], base + BH_OFF + b_base[nh][p] + bswz[kk]);
                        ldsm4(bl[p], base + BL_OFF + b_base[nh][p] + bswz[kk]);
                    }
#pragma unroll
                    for (int p = 0; p < 2; p++)
#pragma unroll
                        for (int q = 0; q < 2; q++) {
                            const int tn = nh * 4 + p * 2 + q;
#pragma unroll
                            for (int tm = 0; tm < 2; tm++) {
                                mma16816(acc[tm][tn], ah[tm], &bh[p][q * 2]);
                                mma16816(acc[tm][tn], al[tm], &bh[p][q * 2]);
                                mma16816(acc[tm][tn], ah[tm], &bl[p][q * 2]);
                            }
                        }
                }
            }
            if (t + 3 < 32) issue_stage(dynb + (u32)((t + 3) & 3) * STAGE_B, tid, m0, n0, t + 3);
            CP_COMMIT();
        }

        // epilogue: tanh(acc + qp) * v into per-row score registers
#pragma unroll
        for (int tm = 0; tm < 2; tm++)
#pragma unroll
            for (int tn = 0; tn < 8; tn++) {
                const int c0 = wn * 64 + tn * 8 + (lane & 3) * 2;
                const float q0 = qs[c0], q1 = qs[c0 + 1];
                const float v0 = vs[c0], v1 = vs[c0 + 1];
                srow[tm * 2 + 0] += tanh_fast(acc[tm][tn][0] + q0) * v0 +
                                    tanh_fast(acc[tm][tn][1] + q1) * v1;
                srow[tm * 2 + 1] += tanh_fast(acc[tm][tn][2] + q0) * v0 +
                                    tanh_fast(acc[tm][tn][3] + q1) * v1;
            }
    }

    // reduce across quads (deterministic), then across the 4 n-warp groups
#pragma unroll
    for (int i = 0; i < 4; i++) {
        srow[i] += __shfl_xor_sync(0xffffffffu, srow[i], 1);
        srow[i] += __shfl_xor_sync(0xffffffffu, srow[i], 2);
    }
    __syncthreads();
    if ((lane & 3) == 0) {
        const int r0 = wm * 32 + (lane >> 2);
        red[wn][r0]      = srow[0];
        red[wn][r0 + 8]  = srow[1];
        red[wn][r0 + 16] = srow[2];
        red[wn][r0 + 24] = srow[3];
    }
    __syncthreads();
    if (tid < 128)
        scores[m0 + tid] = (red[0][tid] + red[1][tid]) + (red[2][tid] + red[3][tid]);
}

// ---------------- K4: softmax over S -----------------------------------------
__global__ void softmax_kernel(float* __restrict__ w) {
    int b = blockIdx.x;
    float* p = w + b * 2048;
    int t = threadIdx.x;
    __shared__ float sm[32];
    float a0 = p[t], a1 = p[t + 1024];
    float m = fmaxf(a0, a1);
#pragma unroll
    for (int o = 16; o; o >>= 1) m = fmaxf(m, __shfl_xor_sync(0xffffffffu, m, o));
    if ((t & 31) == 0) sm[t >> 5] = m;
    __syncthreads();
    if (t < 32) {
        float mm = sm[t];
#pragma unroll
        for (int o = 16; o; o >>= 1) mm = fmaxf(mm, __shfl_xor_sync(0xffffffffu, mm, o));
        sm[t] = mm;
    }
    __syncthreads();
    m = sm[0];
    __syncthreads();
    float e0 = __expf(a0 - m), e1 = __expf(a1 - m);
    float s = e0 + e1;
#pragma unroll
    for (int o = 16; o; o >>= 1) s += __shfl_xor_sync(0xffffffffu, s, o);
    if ((t & 31) == 0) sm[t >> 5] = s;
    __syncthreads();
    if (t < 32) {
        float ss = sm[t];
#pragma unroll
        for (int o = 16; o; o >>= 1) ss += __shfl_xor_sync(0xffffffffu, ss, o);
        sm[t] = ss;
    }
    __syncthreads();
    float inv = 1.0f / sm[0];
    p[t] = e0 * inv;
    p[t + 1024] = e1 * inv;
}

// ---------------- K5/K6: context = w @ values --------------------------------
__global__ void ctx_part_kernel(const float* __restrict__ values, const float* __restrict__ w) {
    int b = blockIdx.x, j = blockIdx.y;
    __shared__ float ws[128];
    int t = threadIdx.x;
    if (t < 128) ws[t] = w[b * 2048 + j * 128 + t];
    __syncthreads();
    const float* V = values + ((size_t)(b * 2048 + j * 128)) * 1024 + t * 4;
    float4 acc = make_float4(0.f, 0.f, 0.f, 0.f);
#pragma unroll 8
    for (int s = 0; s < 128; s++) {
        float4 x = *(const float4*)(V + (size_t)s * 1024);
        float c = ws[s];
        acc.x += c * x.x; acc.y += c * x.y; acc.z += c * x.z; acc.w += c * x.w;
    }
    *(float4*)&g_ctx_part[((size_t)j * 32 + b) * 1024 + t * 4] = acc;
}

__global__ void ctx_reduce_kernel(float* __restrict__ ctx) {
    int b = blockIdx.x, t = threadIdx.x;
    float4 acc = make_float4(0.f, 0.f, 0.f, 0.f);
#pragma unroll
    for (int j = 0; j < 16; j++) {
        float4 x = *(const float4*)&g_ctx_part[((size_t)j * 32 + b) * 1024 + t * 4];
        acc.x += x.x; acc.y += x.y; acc.z += x.z; acc.w += x.w;
    }
    *(float4*)(ctx + b * 1024 + t * 4) = acc;
}

// ---------------- launch ------------------------------------------------------
extern "C" void kernel_launch(void* const* d_in, const int* in_sizes, int n_in,
                              void* d_out, int out_size) {
    const float* query  = (const float*)d_in[0];
    const float* values = (const float*)d_in[1];
    const float* W1     = (const float*)d_in[2];
    const float* W2     = (const float*)d_in[3];
    const float* v      = (const float*)d_in[4];

    float* ctx     = (float*)d_out;
    float* weights = (float*)d_out + 32 * 1024;

    cudaFuncSetAttribute(scores_mma, cudaFuncAttributeMaxDynamicSharedMemorySize, DYN_BYTES);

    qp_kernel<<<dim3(4, 32), 256>>>(query, W2);
    conv_values_kernel<<<65536, 256>>>(values);
    conv_w1_kernel<<<dim3(32, 32), dim3(32, 8)>>>(W1);
    scores_mma<<<512, 512, DYN_BYTES>>>(v, weights);
    softmax_kernel<<<32, 1024>>>(weights);
    ctx_part_kernel<<<dim3(32, 16), 256>>>(values, weights);
    ctx_reduce_kernel<<<32, 256>>>(ctx);
}